// round 12
// baseline (speedup 1.0000x reference)
#include <cuda_runtime.h>
#include <math.h>
#include <stdint.h>

// Problem constants: B=64, S=2048, I=256, H=256, G=2H=512
#define BATCH 64
#define SEQ   2048
#define HID   256
#define GATES 512
#define WROWS 272          // rows in global transposed weights (>=256 zero)
#define ZROW  256          // all-zero row index (sentinel)

// -------- scratch (static device arrays; no allocation) --------
__device__ float g_gx[67108864];          // (B*S, 512) fp32 = 256 MB
__device__ float g_WhT0[WROWS * GATES];   // [j][g]
__device__ float g_WiT1[WROWS * GATES];
__device__ float g_WhT1[WROWS * GATES];

// ---------------------------------------------------------------
// Kernel 0: transpose weights into padded [j][g] layout; zero pad rows.
// ---------------------------------------------------------------
__global__ void prep_kernel(const float* __restrict__ Wh0,
                            const float* __restrict__ Wi1,
                            const float* __restrict__ Wh1)
{
    int idx = blockIdx.x * 256 + threadIdx.x;
    const int perp = WROWS * GATES;
    if (idx < 3 * perp) {
        int m = idx / perp;
        int e = idx - m * perp;
        int j = e >> 9;
        int g = e & 511;
        const float* src = (m == 0) ? Wh0 : (m == 1) ? Wi1 : Wh1;
        float*       dst = (m == 0) ? g_WhT0 : (m == 1) ? g_WiT1 : g_WhT1;
        dst[e] = (j < HID) ? src[g * HID + j] : 0.0f;
    }
}

// ---------------------------------------------------------------
// Kernel 1: gx0 = (x @ Wi0^T + bi0) + bh0   (unchanged — passing)
// ---------------------------------------------------------------
__global__ void __launch_bounds__(256, 2)
gemm_gx_kernel(const float* __restrict__ x,
               const float* __restrict__ Wi0,
               const float* __restrict__ bi0,
               const float* __restrict__ bh0)
{
    __shared__ float As[32][68];
    __shared__ float Bs[32][68];

    const int m0  = blockIdx.x * 64;
    const int n0  = blockIdx.y * 64;
    const int tid = threadIdx.x;
    const int tx  = tid & 15;
    const int ty  = tid >> 4;

    float acc[4][4];
#pragma unroll
    for (int i = 0; i < 4; i++)
#pragma unroll
        for (int j = 0; j < 4; j++) acc[i][j] = 0.f;

    for (int k0 = 0; k0 < 256; k0 += 32) {
#pragma unroll
        for (int v = 0; v < 2; v++) {
            int idx = tid + v * 256;
            int r   = idx >> 3;
            int kk  = (idx & 7) << 2;
            float4 av = *reinterpret_cast<const float4*>(
                x + (size_t)(m0 + r) * 256 + (k0 + kk));
            As[kk + 0][r] = av.x; As[kk + 1][r] = av.y;
            As[kk + 2][r] = av.z; As[kk + 3][r] = av.w;
            float4 bv = *reinterpret_cast<const float4*>(
                Wi0 + (size_t)(n0 + r) * 256 + (k0 + kk));
            Bs[kk + 0][r] = bv.x; Bs[kk + 1][r] = bv.y;
            Bs[kk + 2][r] = bv.z; Bs[kk + 3][r] = bv.w;
        }
        __syncthreads();
#pragma unroll
        for (int k = 0; k < 32; k++) {
            float4 av = *reinterpret_cast<const float4*>(&As[k][ty << 2]);
            float4 bv = *reinterpret_cast<const float4*>(&Bs[k][tx << 2]);
            float aa[4] = {av.x, av.y, av.z, av.w};
            float bb[4] = {bv.x, bv.y, bv.z, bv.w};
#pragma unroll
            for (int i = 0; i < 4; i++)
#pragma unroll
                for (int j = 0; j < 4; j++)
                    acc[i][j] = __fmaf_rn(aa[i], bb[j], acc[i][j]);
        }
        __syncthreads();
    }

    float4 b1 = *reinterpret_cast<const float4*>(bi0 + n0 + (tx << 2));
    float4 b2 = *reinterpret_cast<const float4*>(bh0 + n0 + (tx << 2));

#pragma unroll
    for (int i = 0; i < 4; i++) {
        int r = m0 + (ty << 2) + i;
        float4 o;
        o.x = __fadd_rn(__fadd_rn(acc[i][0], b1.x), b2.x);
        o.y = __fadd_rn(__fadd_rn(acc[i][1], b1.y), b2.y);
        o.z = __fadd_rn(__fadd_rn(acc[i][2], b1.z), b2.z);
        o.w = __fadd_rn(__fadd_rn(acc[i][3], b1.w), b2.w);
        *reinterpret_cast<float4*>(g_gx + (size_t)r * GATES + n0 + (tx << 2)) = o;
    }
}

// ---------------------------------------------------------------
// Cluster helpers (2-CTA clusters)
// ---------------------------------------------------------------
__device__ __forceinline__ unsigned ctarank()
{
    unsigned r;
    asm("mov.u32 %0, %%cluster_ctarank;" : "=r"(r));
    return r;
}

#define CLUSTER_SYNC() do {                                            \
    asm volatile("barrier.cluster.arrive.aligned;" ::: "memory");      \
    asm volatile("barrier.cluster.wait.aligned;"   ::: "memory");      \
} while (0)

__device__ __forceinline__ void remote_st_u32(void* lptr, int rank, unsigned val)
{
    unsigned laddr;
    asm("{ .reg .u64 t; cvta.to.shared.u64 t, %1; cvt.u32.u64 %0, t; }"
        : "=r"(laddr) : "l"(lptr));
    unsigned raddr;
    asm volatile("mapa.shared::cluster.u32 %0, %1, %2;"
                 : "=r"(raddr) : "r"(laddr), "r"(rank));
    asm volatile("st.shared::cluster.u32 [%0], %1;"
                 :: "r"(raddr), "r"(val) : "memory");
}

// XLA logistic: 1/(1+exp(-x)), exp via fp64 rounded to f32 (passing numerics).
__device__ __forceinline__ float sigmoid_ref(float g)
{
    float ef = (float)exp(-(double)g);
    return __fdiv_rn(1.0f, __fadd_rn(1.0f, ef));
}

// ---------------------------------------------------------------
// float4 active-row sum: FOUR gate columns per thread. Each component
// is an independent single-accumulator chain in strictly ascending j
// order (bit-identical to dense ascending-k FMA dot with binary h;
// ZROW pads add exact +0.0f). Batches of 8 rows: 8 independent
// LDG.128 per batch (32 regs), no predication.
// ---------------------------------------------------------------
__device__ __forceinline__ float4 mv4(const float* __restrict__ Wg,
                                      const int* __restrict__ lst, int n16)
{
    float4 m = make_float4(0.f, 0.f, 0.f, 0.f);
    const int4* l4 = reinterpret_cast<const int4*>(lst);
    const int nb = n16 >> 3;           // batches of 8 (n16 multiple of 16)
    for (int k = 0; k < nb; k++) {
        int4 a = l4[k * 2 + 0];
        int4 b = l4[k * 2 + 1];
        float4 w0 = *reinterpret_cast<const float4*>(Wg + ((size_t)a.x << 9));
        float4 w1 = *reinterpret_cast<const float4*>(Wg + ((size_t)a.y << 9));
        float4 w2 = *reinterpret_cast<const float4*>(Wg + ((size_t)a.z << 9));
        float4 w3 = *reinterpret_cast<const float4*>(Wg + ((size_t)a.w << 9));
        float4 w4 = *reinterpret_cast<const float4*>(Wg + ((size_t)b.x << 9));
        float4 w5 = *reinterpret_cast<const float4*>(Wg + ((size_t)b.y << 9));
        float4 w6 = *reinterpret_cast<const float4*>(Wg + ((size_t)b.z << 9));
        float4 w7 = *reinterpret_cast<const float4*>(Wg + ((size_t)b.w << 9));
        m.x = __fadd_rn(m.x, w0.x); m.y = __fadd_rn(m.y, w0.y);
        m.z = __fadd_rn(m.z, w0.z); m.w = __fadd_rn(m.w, w0.w);
        m.x = __fadd_rn(m.x, w1.x); m.y = __fadd_rn(m.y, w1.y);
        m.z = __fadd_rn(m.z, w1.z); m.w = __fadd_rn(m.w, w1.w);
        m.x = __fadd_rn(m.x, w2.x); m.y = __fadd_rn(m.y, w2.y);
        m.z = __fadd_rn(m.z, w2.z); m.w = __fadd_rn(m.w, w2.w);
        m.x = __fadd_rn(m.x, w3.x); m.y = __fadd_rn(m.y, w3.y);
        m.z = __fadd_rn(m.z, w3.z); m.w = __fadd_rn(m.w, w3.w);
        m.x = __fadd_rn(m.x, w4.x); m.y = __fadd_rn(m.y, w4.y);
        m.z = __fadd_rn(m.z, w4.z); m.w = __fadd_rn(m.w, w4.w);
        m.x = __fadd_rn(m.x, w5.x); m.y = __fadd_rn(m.y, w5.y);
        m.z = __fadd_rn(m.z, w5.z); m.w = __fadd_rn(m.w, w5.w);
        m.x = __fadd_rn(m.x, w6.x); m.y = __fadd_rn(m.y, w6.y);
        m.z = __fadd_rn(m.z, w6.z); m.w = __fadd_rn(m.w, w6.w);
        m.x = __fadd_rn(m.x, w7.x); m.y = __fadd_rn(m.y, w7.y);
        m.z = __fadd_rn(m.z, w7.z); m.w = __fadd_rn(m.w, w7.w);
    }
    return m;
}

// local col-quad index k in [0,64) -> global gate col of base (4k)
__device__ __forceinline__ int quadcol(int k, int rank)
{
    int c = 4 * k;
    return (c < 128) ? (rank * 128 + c) : (256 + rank * 128 + (c - 128));
}

// ---------------------------------------------------------------
// Kernel 2: spiking-LSTM scan. 64 clusters x 2 CTAs (128 CTAs).
// CTA rank r owns hidden units [128r,128r+128). Weights stream from
// L1/L2 (no smem carveout). Wh0.h0(t) precomputed in phase 2 of t.
//   phase 1: tid 256-319 (64 thr): Wh1.h1(t-1), float4
//            tid 0-127: L0 update (inline __ldcg gx)
//   phase 2: tid 0-63:  Wi1.h0(t), float4  -> g1s
//            tid 64-127: Wh0.h0(t), float4 -> m0s
// ---------------------------------------------------------------
__global__ void __launch_bounds__(512, 1) __cluster_dims__(2, 1, 1)
recurrent2(const float* __restrict__ bi1,
           const float* __restrict__ bh1,
           float* __restrict__ out)
{
    const int tid  = threadIdx.x;
    const int lane = tid & 31;
    const int warp = tid >> 5;
    const int rank = (int)ctarank();
    const int b    = blockIdx.x >> 1;

    __shared__ float m0s[256];     // Wh0 . h0 (precomputed, local cols)
    __shared__ float mhs[256];     // Wh1 . h1(t-1)
    __shared__ float g1s[256];     // layer-1 gates (local cols)
    __shared__ float c0s[128], c1s[128];
    __shared__ alignas(16) int lst0[WROWS], lst1[WROWS];
    __shared__ unsigned msk0[8], msk1[8];
    __shared__ int n0s, n1s;

    if (tid < 256) m0s[tid] = 0.f;
    if (tid < 128) { c0s[tid] = 0.f; c1s[tid] = 0.f; }
    if (tid == 0)  { n0s = 0; n1s = 0; }
    if (tid < WROWS) { lst0[tid] = ZROW; lst1[tid] = ZROW; }

    // phase-2 per-thread constants (threads 0-63: Wi1 role)
    float4 bi1v = make_float4(0.f, 0.f, 0.f, 0.f);
    float4 bh1v = bi1v;
    if (tid < 64) {
        int g0 = quadcol(tid, rank);
        bi1v = *reinterpret_cast<const float4*>(bi1 + g0);
        bh1v = *reinterpret_cast<const float4*>(bh1 + g0);
    }

    const float* gxb = g_gx + (size_t)b * ((size_t)SEQ * GATES);
    const int ubase  = rank * 128;            // first owned hidden unit
    __syncthreads();

    for (int t = 0; t < SEQ; ++t) {
        // ---------------- phase 1 ----------------
        if (tid >= 256 && tid < 320) {
            // mh = Wh1 . h1(t-1) for local col quad (tid-256)
            int k  = tid - 256;
            int g0 = quadcol(k, rank);
            float4 mh = mv4(g_WhT1 + g0, lst1, n1s);
            *reinterpret_cast<float4*>(&mhs[4 * k]) = mh;
        } else if (tid < 128) {
            // L0 update: gates = gx + m0 (precomputed last step)
            float gxf = __ldcg(gxb + (size_t)t * GATES + (ubase + tid));
            float gxc = __ldcg(gxb + (size_t)t * GATES + (256 + ubase + tid));
            float g  = __fadd_rn(gxf, m0s[tid]);
            float ct = __fadd_rn(gxc, m0s[128 + tid]);
            float f  = sigmoid_ref(g);
            float cc = __fadd_rn(__fmul_rn(f, c0s[tid]),
                                 __fmul_rn(__fsub_rn(1.0f, f), ct));
            c0s[tid] = cc;
            unsigned bal = __ballot_sync(0xffffffffu, cc > 0.f);
            if (lane == 0) {
                msk0[4 * rank + warp] = bal;
                remote_st_u32(&msk0[4 * rank + warp], rank ^ 1, bal);
            }
        }
        CLUSTER_SYNC();                       // masks0 + mhs visible

        // ---------- build lst0 (ascending, 16 ZROW pads) ----------
        if (tid < 256) {
            int j = tid, pre = 0, tot = 0;
            unsigned mw = 0;
#pragma unroll
            for (int w = 0; w < 8; w++) {
                unsigned mm = msk0[w];
                tot += __popc(mm);
                if (w < (j >> 5)) pre += __popc(mm);
                else if (w == (j >> 5)) {
                    mw = mm;
                    pre += __popc(mm & ((1u << (j & 31)) - 1u));
                }
            }
            if ((mw >> (j & 31)) & 1u) lst0[pre] = j;
            if (j < 16) lst0[tot + j] = ZROW;        // tot+15 <= 271
            if (j == 0) n0s = (tot + 15) & ~15;
        }
        __syncthreads();

        // ---------------- phase 2 ----------------
        if (tid < 64) {
            // gates1 = ((Wi1.h0 + bi1) + bh1) + Wh1.h1
            int g0 = quadcol(tid, rank);
            float4 mi = mv4(g_WiT1 + g0, lst0, n0s);
            float4 gi, g2;
            gi.x = __fadd_rn(__fadd_rn(mi.x, bi1v.x), bh1v.x);
            gi.y = __fadd_rn(__fadd_rn(mi.y, bi1v.y), bh1v.y);
            gi.z = __fadd_rn(__fadd_rn(mi.z, bi1v.z), bh1v.z);
            gi.w = __fadd_rn(__fadd_rn(mi.w, bi1v.w), bh1v.w);
            float4 mh = *reinterpret_cast<const float4*>(&mhs[4 * tid]);
            g2.x = __fadd_rn(gi.x, mh.x);
            g2.y = __fadd_rn(gi.y, mh.y);
            g2.z = __fadd_rn(gi.z, mh.z);
            g2.w = __fadd_rn(gi.w, mh.w);
            *reinterpret_cast<float4*>(&g1s[4 * tid]) = g2;
        } else if (tid < 128) {
            // precompute m0' = Wh0 . h0(t) for next step's L0 update
            int k  = tid - 64;
            int g0 = quadcol(k, rank);
            float4 m0 = mv4(g_WhT0 + g0, lst0, n0s);
            *reinterpret_cast<float4*>(&m0s[4 * k]) = m0;
        }
        __syncthreads();

        // ---------------- L1 update + output ----------------
        if (tid < 128) {
            float f  = sigmoid_ref(g1s[tid]);
            float ct = g1s[128 + tid];
            float cc = __fadd_rn(__fmul_rn(f, c1s[tid]),
                                 __fmul_rn(__fsub_rn(1.0f, f), ct));
            c1s[tid] = cc;
            float h  = (cc > 0.f) ? 1.f : 0.f;
            out[((size_t)b * SEQ + t) * HID + (ubase + tid)] = h;
            unsigned bal = __ballot_sync(0xffffffffu, cc > 0.f);
            if (lane == 0) {
                msk1[4 * rank + warp] = bal;
                remote_st_u32(&msk1[4 * rank + warp], rank ^ 1, bal);
            }
        }
        CLUSTER_SYNC();                       // masks1 visible

        // ---------- build lst1 (ascending, 16 ZROW pads) ----------
        if (tid < 256) {
            int j = tid, pre = 0, tot = 0;
            unsigned mw = 0;
#pragma unroll
            for (int w = 0; w < 8; w++) {
                unsigned mm = msk1[w];
                tot += __popc(mm);
                if (w < (j >> 5)) pre += __popc(mm);
                else if (w == (j >> 5)) {
                    mw = mm;
                    pre += __popc(mm & ((1u << (j & 31)) - 1u));
                }
            }
            if ((mw >> (j & 31)) & 1u) lst1[pre] = j;
            if (j < 16) lst1[tot + j] = ZROW;
            if (j == 0) n1s = (tot + 15) & ~15;
        }
        __syncthreads();
    }

    // finals: h_n (2,B,H) then c_n (2,B,H) after the (B,S,H) output
    if (tid < 128) {
        const size_t HN = (size_t)BATCH * SEQ * HID;
        const size_t CN = HN + (size_t)2 * BATCH * HID;
        const int ui = ubase + tid;
        float cc0 = c0s[tid], cc1 = c1s[tid];
        out[HN + ((size_t)0 * BATCH + b) * HID + ui] = (cc0 > 0.f) ? 1.f : 0.f;
        out[HN + ((size_t)1 * BATCH + b) * HID + ui] = (cc1 > 0.f) ? 1.f : 0.f;
        out[CN + ((size_t)0 * BATCH + b) * HID + ui] = cc0;
        out[CN + ((size_t)1 * BATCH + b) * HID + ui] = cc1;
    }
}

// ---------------------------------------------------------------
extern "C" void kernel_launch(void* const* d_in, const int* in_sizes, int n_in,
                              void* d_out, int out_size)
{
    const float* x   = (const float*)d_in[0];
    const float* Wi0 = (const float*)d_in[1];
    const float* bi0 = (const float*)d_in[2];
    const float* Wh0 = (const float*)d_in[3];
    const float* bh0 = (const float*)d_in[4];
    const float* Wi1 = (const float*)d_in[5];
    const float* bi1 = (const float*)d_in[6];
    const float* Wh1 = (const float*)d_in[7];
    const float* bh1 = (const float*)d_in[8];
    float* out = (float*)d_out;

    prep_kernel<<<1632, 256>>>(Wh0, Wi1, Wh1);

    dim3 gg(2048, 8);
    gemm_gx_kernel<<<gg, 256>>>(x, Wi0, bi0, bh0);

    recurrent2<<<BATCH * 2, 512>>>(bi1, bh1, out);
}

// round 13
// speedup vs baseline: 1.6807x; 1.6807x over previous
#include <cuda_runtime.h>
#include <math.h>
#include <stdint.h>

// Problem constants: B=64, S=2048, I=256, H=256, G=2H=512
#define BATCH 64
#define SEQ   2048
#define HID   256
#define GATES 512
#define WROWS 272          // rows in global transposed weights (>=256 zero)
#define ZROW  256          // all-zero row index (sentinel)

// -------- scratch (static device arrays; no allocation) --------
__device__ float g_gx[67108864];          // (B*S, 512) fp32 = 256 MB
__device__ float g_WhT0[WROWS * GATES];   // [j][g]
__device__ float g_WiT1[WROWS * GATES];
__device__ float g_WhT1[WROWS * GATES];

// ---------------------------------------------------------------
// Kernel 0: transpose weights into padded [j][g] layout; zero pad rows.
// ---------------------------------------------------------------
__global__ void prep_kernel(const float* __restrict__ Wh0,
                            const float* __restrict__ Wi1,
                            const float* __restrict__ Wh1)
{
    int idx = blockIdx.x * 256 + threadIdx.x;
    const int perp = WROWS * GATES;
    if (idx < 3 * perp) {
        int m = idx / perp;
        int e = idx - m * perp;
        int j = e >> 9;
        int g = e & 511;
        const float* src = (m == 0) ? Wh0 : (m == 1) ? Wi1 : Wh1;
        float*       dst = (m == 0) ? g_WhT0 : (m == 1) ? g_WiT1 : g_WhT1;
        dst[e] = (j < HID) ? src[g * HID + j] : 0.0f;
    }
}

// ---------------------------------------------------------------
// Kernel 1: gx0 = (x @ Wi0^T + bi0) + bh0   (unchanged — passing)
// ---------------------------------------------------------------
__global__ void __launch_bounds__(256, 2)
gemm_gx_kernel(const float* __restrict__ x,
               const float* __restrict__ Wi0,
               const float* __restrict__ bi0,
               const float* __restrict__ bh0)
{
    __shared__ float As[32][68];
    __shared__ float Bs[32][68];

    const int m0  = blockIdx.x * 64;
    const int n0  = blockIdx.y * 64;
    const int tid = threadIdx.x;
    const int tx  = tid & 15;
    const int ty  = tid >> 4;

    float acc[4][4];
#pragma unroll
    for (int i = 0; i < 4; i++)
#pragma unroll
        for (int j = 0; j < 4; j++) acc[i][j] = 0.f;

    for (int k0 = 0; k0 < 256; k0 += 32) {
#pragma unroll
        for (int v = 0; v < 2; v++) {
            int idx = tid + v * 256;
            int r   = idx >> 3;
            int kk  = (idx & 7) << 2;
            float4 av = *reinterpret_cast<const float4*>(
                x + (size_t)(m0 + r) * 256 + (k0 + kk));
            As[kk + 0][r] = av.x; As[kk + 1][r] = av.y;
            As[kk + 2][r] = av.z; As[kk + 3][r] = av.w;
            float4 bv = *reinterpret_cast<const float4*>(
                Wi0 + (size_t)(n0 + r) * 256 + (k0 + kk));
            Bs[kk + 0][r] = bv.x; Bs[kk + 1][r] = bv.y;
            Bs[kk + 2][r] = bv.z; Bs[kk + 3][r] = bv.w;
        }
        __syncthreads();
#pragma unroll
        for (int k = 0; k < 32; k++) {
            float4 av = *reinterpret_cast<const float4*>(&As[k][ty << 2]);
            float4 bv = *reinterpret_cast<const float4*>(&Bs[k][tx << 2]);
            float aa[4] = {av.x, av.y, av.z, av.w};
            float bb[4] = {bv.x, bv.y, bv.z, bv.w};
#pragma unroll
            for (int i = 0; i < 4; i++)
#pragma unroll
                for (int j = 0; j < 4; j++)
                    acc[i][j] = __fmaf_rn(aa[i], bb[j], acc[i][j]);
        }
        __syncthreads();
    }

    float4 b1 = *reinterpret_cast<const float4*>(bi0 + n0 + (tx << 2));
    float4 b2 = *reinterpret_cast<const float4*>(bh0 + n0 + (tx << 2));

#pragma unroll
    for (int i = 0; i < 4; i++) {
        int r = m0 + (ty << 2) + i;
        float4 o;
        o.x = __fadd_rn(__fadd_rn(acc[i][0], b1.x), b2.x);
        o.y = __fadd_rn(__fadd_rn(acc[i][1], b1.y), b2.y);
        o.z = __fadd_rn(__fadd_rn(acc[i][2], b1.z), b2.z);
        o.w = __fadd_rn(__fadd_rn(acc[i][3], b1.w), b2.w);
        *reinterpret_cast<float4*>(g_gx + (size_t)r * GATES + n0 + (tx << 2)) = o;
    }
}

// ---------------------------------------------------------------
// Cluster helpers (2-CTA clusters)
// ---------------------------------------------------------------
__device__ __forceinline__ unsigned ctarank()
{
    unsigned r;
    asm("mov.u32 %0, %%cluster_ctarank;" : "=r"(r));
    return r;
}

#define CLUSTER_SYNC() do {                                            \
    asm volatile("barrier.cluster.arrive.aligned;" ::: "memory");      \
    asm volatile("barrier.cluster.wait.aligned;"   ::: "memory");      \
} while (0)

__device__ __forceinline__ void remote_st_u32(void* lptr, int rank, unsigned val)
{
    unsigned laddr;
    asm("{ .reg .u64 t; cvta.to.shared.u64 t, %1; cvt.u32.u64 %0, t; }"
        : "=r"(laddr) : "l"(lptr));
    unsigned raddr;
    asm volatile("mapa.shared::cluster.u32 %0, %1, %2;"
                 : "=r"(raddr) : "r"(laddr), "r"(rank));
    asm volatile("st.shared::cluster.u32 [%0], %1;"
                 :: "r"(raddr), "r"(val) : "memory");
}

// XLA logistic: 1/(1+exp(-x)), exp via fp64 rounded to f32 (passing numerics).
__device__ __forceinline__ float sigmoid_ref(float g)
{
    float ef = (float)exp(-(double)g);
    return __fdiv_rn(1.0f, __fadd_rn(1.0f, ef));
}

// ---------------------------------------------------------------
// float2 active-row sum (proven bit-exact in round 7): two independent
// single-accumulator chains in strictly ascending j order; ZROW pads
// add exact +0.0f. 16 independent LDG.64 per batch -> MLP=16/thread.
// ---------------------------------------------------------------
__device__ __forceinline__ float2 mv2(const float* __restrict__ Wb,
                                      const int* __restrict__ lst, int n16)
{
    float2 m = make_float2(0.f, 0.f);
    const int4* l4 = reinterpret_cast<const int4*>(lst);
    const int nb = n16 >> 4;
    for (int k = 0; k < nb; k++) {
        int4 a = l4[k * 4 + 0];
        int4 b = l4[k * 4 + 1];
        int4 c = l4[k * 4 + 2];
        int4 d = l4[k * 4 + 3];
        float2 w0  = *reinterpret_cast<const float2*>(Wb + ((size_t)a.x << 9));
        float2 w1  = *reinterpret_cast<const float2*>(Wb + ((size_t)a.y << 9));
        float2 w2  = *reinterpret_cast<const float2*>(Wb + ((size_t)a.z << 9));
        float2 w3  = *reinterpret_cast<const float2*>(Wb + ((size_t)a.w << 9));
        float2 w4  = *reinterpret_cast<const float2*>(Wb + ((size_t)b.x << 9));
        float2 w5  = *reinterpret_cast<const float2*>(Wb + ((size_t)b.y << 9));
        float2 w6  = *reinterpret_cast<const float2*>(Wb + ((size_t)b.z << 9));
        float2 w7  = *reinterpret_cast<const float2*>(Wb + ((size_t)b.w << 9));
        float2 w8  = *reinterpret_cast<const float2*>(Wb + ((size_t)c.x << 9));
        float2 w9  = *reinterpret_cast<const float2*>(Wb + ((size_t)c.y << 9));
        float2 w10 = *reinterpret_cast<const float2*>(Wb + ((size_t)c.z << 9));
        float2 w11 = *reinterpret_cast<const float2*>(Wb + ((size_t)c.w << 9));
        float2 w12 = *reinterpret_cast<const float2*>(Wb + ((size_t)d.x << 9));
        float2 w13 = *reinterpret_cast<const float2*>(Wb + ((size_t)d.y << 9));
        float2 w14 = *reinterpret_cast<const float2*>(Wb + ((size_t)d.z << 9));
        float2 w15 = *reinterpret_cast<const float2*>(Wb + ((size_t)d.w << 9));
        m.x = __fadd_rn(m.x, w0.x);  m.y = __fadd_rn(m.y, w0.y);
        m.x = __fadd_rn(m.x, w1.x);  m.y = __fadd_rn(m.y, w1.y);
        m.x = __fadd_rn(m.x, w2.x);  m.y = __fadd_rn(m.y, w2.y);
        m.x = __fadd_rn(m.x, w3.x);  m.y = __fadd_rn(m.y, w3.y);
        m.x = __fadd_rn(m.x, w4.x);  m.y = __fadd_rn(m.y, w4.y);
        m.x = __fadd_rn(m.x, w5.x);  m.y = __fadd_rn(m.y, w5.y);
        m.x = __fadd_rn(m.x, w6.x);  m.y = __fadd_rn(m.y, w6.y);
        m.x = __fadd_rn(m.x, w7.x);  m.y = __fadd_rn(m.y, w7.y);
        m.x = __fadd_rn(m.x, w8.x);  m.y = __fadd_rn(m.y, w8.y);
        m.x = __fadd_rn(m.x, w9.x);  m.y = __fadd_rn(m.y, w9.y);
        m.x = __fadd_rn(m.x, w10.x); m.y = __fadd_rn(m.y, w10.y);
        m.x = __fadd_rn(m.x, w11.x); m.y = __fadd_rn(m.y, w11.y);
        m.x = __fadd_rn(m.x, w12.x); m.y = __fadd_rn(m.y, w12.y);
        m.x = __fadd_rn(m.x, w13.x); m.y = __fadd_rn(m.y, w13.y);
        m.x = __fadd_rn(m.x, w14.x); m.y = __fadd_rn(m.y, w14.y);
        m.x = __fadd_rn(m.x, w15.x); m.y = __fadd_rn(m.y, w15.y);
    }
    return m;
}

// local pair index k in [0,128) -> global gate col of pair base 2k
__device__ __forceinline__ int paircol(int k, int rank)
{
    int c = 2 * k;
    return (c < 128) ? (rank * 128 + c) : (256 + rank * 128 + (c - 128));
}

// ---------------------------------------------------------------
// Kernel 2: spiking-LSTM scan, depth-2 pipelined. 64 clusters x 2 CTAs.
// CTA rank r owns hidden units [128r,128r+128). One matvec phase + one
// update phase + ONE cluster sync per step.
//   update phase (step t): warps 0-3: L0(t) using m0s+gxs;
//                          warps 4-7: L1(t-1) using g1s+mhs (output row t-1)
//   [cluster sync; build lst0(t) and lst1(t-1)]
//   matvec phase: tid 0-127: Wi1.h0(t) -> g1s | tid 128-255: Wh0.h0(t) -> m0s
//                 tid 256-383: Wh1.h1(t-1) -> mhs | tid 384-511: gx prefetch
// ---------------------------------------------------------------
__global__ void __launch_bounds__(512, 1) __cluster_dims__(2, 1, 1)
recurrent2(const float* __restrict__ bi1,
           const float* __restrict__ bh1,
           float* __restrict__ out)
{
    const int tid  = threadIdx.x;
    const int lane = tid & 31;
    const int warp = tid >> 5;
    const int rank = (int)ctarank();
    const int b    = blockIdx.x >> 1;

    __shared__ float gxs[512];     // double-buffered gx [2][256]
    __shared__ float m0s[256];     // Wh0 . h0(t-1) (precomputed)
    __shared__ float mhs[256];     // Wh1 . h1(t-2->t-1) (precomputed)
    __shared__ float g1s[256];     // (Wi1.h0 + bi1) + bh1 (precomputed)
    __shared__ float c0s[128], c1s[128];
    __shared__ alignas(16) int lst0[WROWS], lst1[WROWS];
    __shared__ unsigned msk0[8], msk1[8];
    __shared__ int n0s, n1s;

    if (tid < 256) m0s[tid] = 0.f;
    if (tid < 128) { c0s[tid] = 0.f; c1s[tid] = 0.f; }
    if (tid < 8)   { msk0[tid] = 0u; msk1[tid] = 0u; }
    if (tid == 0)  { n0s = 0; n1s = 0; }
    if (tid < WROWS) { lst0[tid] = ZROW; lst1[tid] = ZROW; }

    // biases for Wi1 threads (tid<128), float2 per pair
    float2 bi1v = make_float2(0.f, 0.f), bh1v = bi1v;
    if (tid < 128) {
        int g0 = paircol(tid, rank);
        bi1v = *reinterpret_cast<const float2*>(bi1 + g0);
        bh1v = *reinterpret_cast<const float2*>(bh1 + g0);
    }

    const float* gxb = g_gx + (size_t)b * ((size_t)SEQ * GATES);
    const int ubase  = rank * 128;

    // prefetch gx(0) into buffer 0
    if (tid >= 384) {
        int v = tid - 384;
        gxs[v]       = __ldcg(gxb + (ubase + v));
        gxs[128 + v] = __ldcg(gxb + (256 + ubase + v));
    }
    __syncthreads();

    for (int t = 0; t < SEQ; ++t) {
        const int pb = (t & 1) * 256;

        // ---------------- update phase ----------------
        if (tid < 128) {
            // L0(t): gates = gx(t) + Wh0.h0(t-1)
            float g  = __fadd_rn(gxs[pb + tid],       m0s[tid]);
            float ct = __fadd_rn(gxs[pb + 128 + tid], m0s[128 + tid]);
            float f  = sigmoid_ref(g);
            float cc = __fadd_rn(__fmul_rn(f, c0s[tid]),
                                 __fmul_rn(__fsub_rn(1.0f, f), ct));
            c0s[tid] = cc;
            unsigned bal = __ballot_sync(0xffffffffu, cc > 0.f);
            if (lane == 0) {
                msk0[4 * rank + warp] = bal;
                remote_st_u32(&msk0[4 * rank + warp], rank ^ 1, bal);
            }
        } else if (tid < 256 && t > 0) {
            // L1(t-1): gates = ((Wi1.h0+bi1)+bh1) + Wh1.h1(t-2)
            int v = tid - 128;
            float g  = __fadd_rn(g1s[v],       mhs[v]);
            float ct = __fadd_rn(g1s[128 + v], mhs[128 + v]);
            float f  = sigmoid_ref(g);
            float cc = __fadd_rn(__fmul_rn(f, c1s[v]),
                                 __fmul_rn(__fsub_rn(1.0f, f), ct));
            c1s[v] = cc;
            float h = (cc > 0.f) ? 1.f : 0.f;
            out[((size_t)b * SEQ + (t - 1)) * HID + (ubase + v)] = h;
            unsigned bal = __ballot_sync(0xffffffffu, cc > 0.f);
            if (lane == 0) {
                msk1[4 * rank + (warp - 4)] = bal;
                remote_st_u32(&msk1[4 * rank + (warp - 4)], rank ^ 1, bal);
            }
        }
        CLUSTER_SYNC();                        // both masks visible

        // ---------- builds: lst0(t) and lst1(t-1), ascending ----------
        if (tid < 256) {
            int j = tid, pre = 0, tot = 0;
            unsigned mw = 0;
#pragma unroll
            for (int w = 0; w < 8; w++) {
                unsigned mm = msk0[w];
                tot += __popc(mm);
                if (w < (j >> 5)) pre += __popc(mm);
                else if (w == (j >> 5)) {
                    mw = mm;
                    pre += __popc(mm & ((1u << (j & 31)) - 1u));
                }
            }
            if ((mw >> (j & 31)) & 1u) lst0[pre] = j;
            if (j < 16) lst0[tot + j] = ZROW;
            if (j == 0) n0s = (tot + 15) & ~15;
        } else {
            int j = tid - 256, pre = 0, tot = 0;
            unsigned mw = 0;
#pragma unroll
            for (int w = 0; w < 8; w++) {
                unsigned mm = msk1[w];
                tot += __popc(mm);
                if (w < (j >> 5)) pre += __popc(mm);
                else if (w == (j >> 5)) {
                    mw = mm;
                    pre += __popc(mm & ((1u << (j & 31)) - 1u));
                }
            }
            if ((mw >> (j & 31)) & 1u) lst1[pre] = j;
            if (j < 16) lst1[tot + j] = ZROW;
            if (j == 0) n1s = (tot + 15) & ~15;
        }
        __syncthreads();

        // ---------------- matvec phase (all three concurrent) ----------
        if (tid < 128) {
            int g0 = paircol(tid, rank);
            float2 mi = mv2(g_WiT1 + g0, lst0, n0s);
            float2 gi;
            gi.x = __fadd_rn(__fadd_rn(mi.x, bi1v.x), bh1v.x);
            gi.y = __fadd_rn(__fadd_rn(mi.y, bi1v.y), bh1v.y);
            *reinterpret_cast<float2*>(&g1s[2 * tid]) = gi;
        } else if (tid < 256) {
            int k  = tid - 128;
            int g0 = paircol(k, rank);
            float2 m0 = mv2(g_WhT0 + g0, lst0, n0s);
            *reinterpret_cast<float2*>(&m0s[2 * k]) = m0;
        } else if (tid < 384) {
            int k  = tid - 256;
            int g0 = paircol(k, rank);
            float2 mh = mv2(g_WhT1 + g0, lst1, n1s);
            *reinterpret_cast<float2*>(&mhs[2 * k]) = mh;
        } else {
            int tn = t + 1;
            if (tn < SEQ) {
                int v  = tid - 384;
                int nb = (tn & 1) * 256;
                gxs[nb + v]       = __ldcg(gxb + (size_t)tn * GATES + (ubase + v));
                gxs[nb + 128 + v] = __ldcg(gxb + (size_t)tn * GATES + (256 + ubase + v));
            }
        }
        __syncthreads();
    }

    // -------- epilogue: L1 update for step SEQ-1 --------
    if (tid < 128) {
        float g  = __fadd_rn(g1s[tid],       mhs[tid]);
        float ct = __fadd_rn(g1s[128 + tid], mhs[128 + tid]);
        float f  = sigmoid_ref(g);
        float cc = __fadd_rn(__fmul_rn(f, c1s[tid]),
                             __fmul_rn(__fsub_rn(1.0f, f), ct));
        c1s[tid] = cc;
        out[((size_t)b * SEQ + (SEQ - 1)) * HID + (ubase + tid)] =
            (cc > 0.f) ? 1.f : 0.f;
    }
    __syncthreads();

    // finals: h_n (2,B,H) then c_n (2,B,H) after the (B,S,H) output
    if (tid < 128) {
        const size_t HN = (size_t)BATCH * SEQ * HID;
        const size_t CN = HN + (size_t)2 * BATCH * HID;
        const int ui = ubase + tid;
        float cc0 = c0s[tid], cc1 = c1s[tid];
        out[HN + ((size_t)0 * BATCH + b) * HID + ui] = (cc0 > 0.f) ? 1.f : 0.f;
        out[HN + ((size_t)1 * BATCH + b) * HID + ui] = (cc1 > 0.f) ? 1.f : 0.f;
        out[CN + ((size_t)0 * BATCH + b) * HID + ui] = cc0;
        out[CN + ((size_t)1 * BATCH + b) * HID + ui] = cc1;
    }
}

// ---------------------------------------------------------------
extern "C" void kernel_launch(void* const* d_in, const int* in_sizes, int n_in,
                              void* d_out, int out_size)
{
    const float* x   = (const float*)d_in[0];
    const float* Wi0 = (const float*)d_in[1];
    const float* bi0 = (const float*)d_in[2];
    const float* Wh0 = (const float*)d_in[3];
    const float* bh0 = (const float*)d_in[4];
    const float* Wi1 = (const float*)d_in[5];
    const float* bi1 = (const float*)d_in[6];
    const float* Wh1 = (const float*)d_in[7];
    const float* bh1 = (const float*)d_in[8];
    float* out = (float*)d_out;

    prep_kernel<<<1632, 256>>>(Wh0, Wi1, Wh1);

    dim3 gg(2048, 8);
    gemm_gx_kernel<<<gg, 256>>>(x, Wi0, bi0, bh0);

    recurrent2<<<BATCH * 2, 512>>>(bi1, bh1, out);
}